// round 3
// baseline (speedup 1.0000x reference)
#include <cuda_runtime.h>

// PixelPrototypeDistanceLoss — B=8, D=256, H=W=128, C=19, IGNORE=19 (fixed by setup_inputs)
// loss = mean over valid pixels of (1 - emb[b,:,h,w] . Q[lb]) ^ 2
//
// HBM-bound: 134 MB emb read once. Design:
//  - 1 thread / pixel, hw fastest -> coalesced 128B/warp per d-step, __ldcs streaming
//  - Q staged in SMEM with stride 257 (bank = (c+d) mod 32 -> conflict-free gather)
//  - block partials -> __device__ scratch (deterministic, no atomics, no zero pass;
//    every block overwrites its slot every launch -> graph-replay safe)
//  - final 1-block double reduce + divide
//
// NOTE: lb is int32 on device (JAX x64 disabled downcasts jnp.int64 -> int32).

constexpr int Bv = 8, Dv = 256, Hv = 128, Wv = 128, Cv = 19, IGNORE = 19;
constexpr int HW = Hv * Wv;                     // 16384
constexpr long long NPIX = (long long)Bv * HW;  // 131072
constexpr int THREADS = 256;
constexpr int NBLOCKS = (int)(NPIX / THREADS);  // 512
constexpr int QSTRIDE = Dv + 1;                 // 257: breaks 32-bank alignment of class rows

__device__ float g_bsum[NBLOCKS];
__device__ float g_bcnt[NBLOCKS];

__global__ void __launch_bounds__(THREADS)
ppd_main(const float* __restrict__ emb,
         const int* __restrict__ lb,
         const float* __restrict__ Q) {
    __shared__ float Qs[Cv * QSTRIDE];   // ~19.5 KB

    const int tid = threadIdx.x;

    // Stage Q [19,256] -> padded SMEM
    for (int i = tid; i < Cv * Dv; i += THREADS) {
        const int c = i >> 8;            // D == 256
        const int d = i & (Dv - 1);
        Qs[c * QSTRIDE + d] = Q[i];
    }
    __syncthreads();

    const int n  = blockIdx.x * THREADS + tid;   // pixel id, exact multiple (no tail)
    const int b  = n >> 14;                      // n / HW
    const int hw = n & (HW - 1);

    const int   c     = lb[n];
    const bool  valid = (c != IGNORE);
    const float* q    = &Qs[(valid ? c : 0) * QSTRIDE];

    const float* ep = emb + (long long)b * Dv * HW + hw;

    float acc = 0.0f;
#pragma unroll 8
    for (int d = 0; d < Dv; ++d) {
        acc = fmaf(__ldcs(ep + (long long)d * HW), q[d], acc);
    }

    const float r   = 1.0f - acc;
    float sq  = valid ? r * r : 0.0f;
    float cnt = valid ? 1.0f : 0.0f;

    // intra-warp reduce
#pragma unroll
    for (int o = 16; o > 0; o >>= 1) {
        sq  += __shfl_down_sync(0xFFFFFFFFu, sq,  o);
        cnt += __shfl_down_sync(0xFFFFFFFFu, cnt, o);
    }

    __shared__ float s_sq[THREADS / 32];
    __shared__ float s_ct[THREADS / 32];
    const int wid  = tid >> 5;
    const int lane = tid & 31;
    if (lane == 0) { s_sq[wid] = sq; s_ct[wid] = cnt; }
    __syncthreads();

    if (wid == 0) {
        float s = (lane < THREADS / 32) ? s_sq[lane] : 0.0f;
        float k = (lane < THREADS / 32) ? s_ct[lane] : 0.0f;
#pragma unroll
        for (int o = 4; o > 0; o >>= 1) {
            s += __shfl_down_sync(0xFFFFFFFFu, s, o);
            k += __shfl_down_sync(0xFFFFFFFFu, k, o);
        }
        if (lane == 0) {
            g_bsum[blockIdx.x] = s;
            g_bcnt[blockIdx.x] = k;
        }
    }
}

__global__ void __launch_bounds__(NBLOCKS)
ppd_final(float* __restrict__ out) {
    const int t = threadIdx.x;           // 512 threads, one per block-partial
    double s = (double)g_bsum[t];
    double k = (double)g_bcnt[t];

#pragma unroll
    for (int o = 16; o > 0; o >>= 1) {
        s += __shfl_down_sync(0xFFFFFFFFu, s, o);
        k += __shfl_down_sync(0xFFFFFFFFu, k, o);
    }

    __shared__ double sh_s[NBLOCKS / 32];
    __shared__ double sh_k[NBLOCKS / 32];
    const int wid  = t >> 5;
    const int lane = t & 31;
    if (lane == 0) { sh_s[wid] = s; sh_k[wid] = k; }
    __syncthreads();

    if (wid == 0) {
        double a = (lane < NBLOCKS / 32) ? sh_s[lane] : 0.0;
        double c = (lane < NBLOCKS / 32) ? sh_k[lane] : 0.0;
#pragma unroll
        for (int o = 8; o > 0; o >>= 1) {
            a += __shfl_down_sync(0xFFFFFFFFu, a, o);
            c += __shfl_down_sync(0xFFFFFFFFu, c, o);
        }
        if (lane == 0) out[0] = (float)(a / c);
    }
}

extern "C" void kernel_launch(void* const* d_in, const int* in_sizes, int n_in,
                              void* d_out, int out_size) {
    const float* emb = (const float*)d_in[0];   // [8,256,128,128] f32
    const int*   lb  = (const int*)d_in[1];     // [8,128,128] i32 (JAX x64 off)
    const float* Q   = (const float*)d_in[2];   // [19,256] f32
    float*       out = (float*)d_out;           // scalar f32

    (void)in_sizes; (void)n_in; (void)out_size;

    ppd_main<<<NBLOCKS, THREADS>>>(emb, lb, Q);
    ppd_final<<<1, NBLOCKS>>>(out);
}

// round 4
// speedup vs baseline: 1.1181x; 1.1181x over previous
#include <cuda_runtime.h>

// PixelPrototypeDistanceLoss — B=8, D=256, H=W=128, C=19, IGNORE=19
// loss = mean over valid pixels of (1 - emb[b,:,h,w] . Q[lb]) ^ 2
//
// R4: single fused kernel.
//  - thread-per-pixel, hw fastest -> 128B/warp coalesced per d-step, __ldcs streaming
//  - explicit unroll-16 front-batched loads: 2KB outstanding/warp (55KB/SM) to cover
//    DRAM latency (need ~25KB/SM) — fixes the 4.5 TB/s ceiling seen in R3
//  - Q in SMEM stride 257 (conflict-free gather)
//  - last-block-done pattern (threadfence + atomic counter, counter self-resets)
//    replaces the 4.9us ppd_final launch
//
// lb is int32 on device (JAX x64 disabled).

constexpr int Bv = 8, Dv = 256, Hv = 128, Wv = 128, Cv = 19, IGNORE = 19;
constexpr int HW = Hv * Wv;                     // 16384
constexpr long long NPIX = (long long)Bv * HW;  // 131072
constexpr int THREADS = 256;
constexpr int NBLOCKS = (int)(NPIX / THREADS);  // 512
constexpr int QSTRIDE = Dv + 1;                 // 257
constexpr int UNROLL = 16;

__device__ float g_bsum[NBLOCKS];
__device__ float g_bcnt[NBLOCKS];
__device__ unsigned int g_count = 0;            // reset to 0 by last block each launch

__global__ void __launch_bounds__(THREADS)
ppd_fused(const float* __restrict__ emb,
          const int* __restrict__ lb,
          const float* __restrict__ Q,
          float* __restrict__ out) {
    __shared__ float Qs[Cv * QSTRIDE];          // ~19.5 KB
    __shared__ float s_sq[THREADS / 32];
    __shared__ float s_ct[THREADS / 32];
    __shared__ double sh_s[THREADS / 32];
    __shared__ double sh_k[THREADS / 32];
    __shared__ int s_last;

    const int tid = threadIdx.x;
    const int n   = blockIdx.x * THREADS + tid; // pixel id (grid covers exactly NPIX)

    // label load first (independent of SMEM staging)
    const int  c     = lb[n];
    const bool valid = (c != IGNORE);

    // Stage Q [19,256] -> padded SMEM
    for (int i = tid; i < Cv * Dv; i += THREADS) {
        const int cc = i >> 8;                  // D == 256
        const int dd = i & (Dv - 1);
        Qs[cc * QSTRIDE + dd] = Q[i];
    }
    __syncthreads();

    const int b  = n >> 14;                     // n / HW
    const int hw = n & (HW - 1);
    const float* q  = &Qs[(valid ? c : 0) * QSTRIDE];
    const float* ep = emb + (long long)b * Dv * HW + hw;

    float acc = 0.0f;
    for (int d0 = 0; d0 < Dv; d0 += UNROLL) {
        float v[UNROLL];
#pragma unroll
        for (int j = 0; j < UNROLL; ++j)
            v[j] = __ldcs(ep + (long long)(d0 + j) * HW);   // 16 batched LDGs
        float qv[UNROLL];
#pragma unroll
        for (int j = 0; j < UNROLL; ++j)
            qv[j] = q[d0 + j];
#pragma unroll
        for (int j = 0; j < UNROLL; ++j)
            acc = fmaf(v[j], qv[j], acc);
    }

    const float r = 1.0f - acc;
    float sq  = valid ? r * r : 0.0f;
    float cnt = valid ? 1.0f : 0.0f;

    // intra-warp reduce
#pragma unroll
    for (int o = 16; o > 0; o >>= 1) {
        sq  += __shfl_down_sync(0xFFFFFFFFu, sq,  o);
        cnt += __shfl_down_sync(0xFFFFFFFFu, cnt, o);
    }

    const int wid  = tid >> 5;
    const int lane = tid & 31;
    if (lane == 0) { s_sq[wid] = sq; s_ct[wid] = cnt; }
    __syncthreads();

    if (tid == 0) {
        float s = 0.0f, k = 0.0f;
#pragma unroll
        for (int w = 0; w < THREADS / 32; ++w) { s += s_sq[w]; k += s_ct[w]; }
        g_bsum[blockIdx.x] = s;
        g_bcnt[blockIdx.x] = k;
        __threadfence();                         // partials visible before ticket
        const unsigned prev = atomicAdd(&g_count, 1u);
        s_last = (prev == (unsigned)(NBLOCKS - 1));
    }
    __syncthreads();

    if (s_last) {
        // last block: reduce 512 partials (L1-bypass loads; written by other SMs)
        double a = 0.0, k = 0.0;
        for (int i = tid; i < NBLOCKS; i += THREADS) {
            a += (double)__ldcg(&g_bsum[i]);
            k += (double)__ldcg(&g_bcnt[i]);
        }
#pragma unroll
        for (int o = 16; o > 0; o >>= 1) {
            a += __shfl_down_sync(0xFFFFFFFFu, a, o);
            k += __shfl_down_sync(0xFFFFFFFFu, k, o);
        }
        if (lane == 0) { sh_s[wid] = a; sh_k[wid] = k; }
        __syncthreads();
        if (wid == 0) {
            double aa = (lane < THREADS / 32) ? sh_s[lane] : 0.0;
            double kk = (lane < THREADS / 32) ? sh_k[lane] : 0.0;
#pragma unroll
            for (int o = 4; o > 0; o >>= 1) {
                aa += __shfl_down_sync(0xFFFFFFFFu, aa, o);
                kk += __shfl_down_sync(0xFFFFFFFFu, kk, o);
            }
            if (lane == 0) {
                out[0] = (float)(aa / kk);
                g_count = 0;                     // rearm for next graph replay
            }
        }
    }
}

extern "C" void kernel_launch(void* const* d_in, const int* in_sizes, int n_in,
                              void* d_out, int out_size) {
    const float* emb = (const float*)d_in[0];   // [8,256,128,128] f32
    const int*   lb  = (const int*)d_in[1];     // [8,128,128] i32
    const float* Q   = (const float*)d_in[2];   // [19,256] f32
    float*       out = (float*)d_out;           // scalar f32

    (void)in_sizes; (void)n_in; (void)out_size;

    ppd_fused<<<NBLOCKS, THREADS>>>(emb, lb, Q, out);
}

// round 7
// speedup vs baseline: 1.1403x; 1.0199x over previous
#include <cuda_runtime.h>

// PixelPrototypeDistanceLoss — B=8, D=256, H=W=128, C=19, IGNORE=19
// loss = mean over valid pixels of (1 - emb[b,:,h,w] . Q[lb]) ^ 2
//
// R7 == R5/R6 resubmitted verbatim (neither ran: broker infra failures).
// Theory under test: float4 / 4-pixels-per-thread fixes MLP (R4: regs=31 showed
// ptxas de-batched the scalar unroll-16 -> ~21-27KB in flight/SM -> 48% DRAM).
//  - LDG.128, 16-deep batch, constant immediate offsets (j*64KB < +-8MB)
//  - __launch_bounds__(128,4): allows 128 regs so the 64-reg float4 batch stays live
//  - Q in SMEM stride 257 (conflict-free gather, broadcast on equal labels)
//  - fused last-block-done reduction (counter self-rearms for graph replay;
//    no spin-waits anywhere -> cannot hang)
//
// lb is int32 on device (JAX x64 disabled).

constexpr int Bv = 8, Dv = 256, Hv = 128, Wv = 128, Cv = 19, IGNORE = 19;
constexpr int HW = Hv * Wv;                     // 16384
constexpr long long NPIX = (long long)Bv * HW;  // 131072
constexpr int PX_PER_THREAD = 4;
constexpr int THREADS = 128;
constexpr int NBLOCKS = (int)(NPIX / (THREADS * PX_PER_THREAD));  // 256
constexpr int QSTRIDE = Dv + 1;                 // 257
constexpr int UNROLL = 16;
constexpr int HW4 = HW / 4;                     // float4 stride per d

__device__ float g_bsum[NBLOCKS];
__device__ float g_bcnt[NBLOCKS];
__device__ unsigned int g_count = 0;            // rearmed by last block each launch

__global__ void __launch_bounds__(THREADS, 4)
ppd_fused(const float4* __restrict__ emb4,
          const int4* __restrict__ lb4,
          const float* __restrict__ Q,
          float* __restrict__ out) {
    __shared__ float Qs[Cv * QSTRIDE];          // ~19.5 KB
    __shared__ float s_sq[THREADS / 32];
    __shared__ float s_ct[THREADS / 32];
    __shared__ double sh_s[THREADS / 32];
    __shared__ double sh_k[THREADS / 32];
    __shared__ int s_last;

    const int tid = threadIdx.x;
    const int t4  = blockIdx.x * THREADS + tid; // float4-group id
    const int n0  = t4 * 4;                     // first pixel id of this thread

    // 4 labels (one int4 load)
    const int4 lbv = lb4[t4];
    const bool v0 = lbv.x != IGNORE, v1 = lbv.y != IGNORE,
               v2 = lbv.z != IGNORE, v3 = lbv.w != IGNORE;

    // Stage Q [19,256] -> padded SMEM
    for (int i = tid; i < Cv * Dv; i += THREADS) {
        const int cc = i >> 8;
        const int dd = i & (Dv - 1);
        Qs[cc * QSTRIDE + dd] = Q[i];
    }
    __syncthreads();

    const float* q0 = &Qs[(v0 ? lbv.x : 0) * QSTRIDE];
    const float* q1 = &Qs[(v1 ? lbv.y : 0) * QSTRIDE];
    const float* q2 = &Qs[(v2 ? lbv.z : 0) * QSTRIDE];
    const float* q3 = &Qs[(v3 ? lbv.w : 0) * QSTRIDE];

    const int b   = n0 >> 14;                   // blocks never straddle batch images
    const int hw  = n0 & (HW - 1);
    const float4* ep = emb4 + ((long long)b * Dv * HW + hw) / 4;

    float a0 = 0.f, a1 = 0.f, a2 = 0.f, a3 = 0.f;

    for (int d0 = 0; d0 < Dv; d0 += UNROLL) {
        float4 v[UNROLL];
#pragma unroll
        for (int j = 0; j < UNROLL; ++j)
            v[j] = __ldcs(ep + (long long)(d0 + j) * HW4);  // LDG.128, imm offsets
#pragma unroll
        for (int j = 0; j < UNROLL; ++j) {
            const int d = d0 + j;
            a0 = fmaf(v[j].x, q0[d], a0);
            a1 = fmaf(v[j].y, q1[d], a1);
            a2 = fmaf(v[j].z, q2[d], a2);
            a3 = fmaf(v[j].w, q3[d], a3);
        }
    }

    const float r0 = 1.0f - a0, r1 = 1.0f - a1, r2 = 1.0f - a2, r3 = 1.0f - a3;
    float sq  = (v0 ? r0 * r0 : 0.f) + (v1 ? r1 * r1 : 0.f)
              + (v2 ? r2 * r2 : 0.f) + (v3 ? r3 * r3 : 0.f);
    float cnt = (float)v0 + (float)v1 + (float)v2 + (float)v3;

#pragma unroll
    for (int o = 16; o > 0; o >>= 1) {
        sq  += __shfl_down_sync(0xFFFFFFFFu, sq,  o);
        cnt += __shfl_down_sync(0xFFFFFFFFu, cnt, o);
    }

    const int wid  = tid >> 5;
    const int lane = tid & 31;
    if (lane == 0) { s_sq[wid] = sq; s_ct[wid] = cnt; }
    __syncthreads();

    if (tid == 0) {
        float s = 0.f, k = 0.f;
#pragma unroll
        for (int w = 0; w < THREADS / 32; ++w) { s += s_sq[w]; k += s_ct[w]; }
        g_bsum[blockIdx.x] = s;
        g_bcnt[blockIdx.x] = k;
        __threadfence();
        const unsigned prev = atomicAdd(&g_count, 1u);
        s_last = (prev == (unsigned)(NBLOCKS - 1));
    }
    __syncthreads();

    if (s_last) {
        double a = 0.0, k = 0.0;
        for (int i = tid; i < NBLOCKS; i += THREADS) {
            a += (double)__ldcg(&g_bsum[i]);
            k += (double)__ldcg(&g_bcnt[i]);
        }
#pragma unroll
        for (int o = 16; o > 0; o >>= 1) {
            a += __shfl_down_sync(0xFFFFFFFFu, a, o);
            k += __shfl_down_sync(0xFFFFFFFFu, k, o);
        }
        if (lane == 0) { sh_s[wid] = a; sh_k[wid] = k; }
        __syncthreads();
        if (wid == 0) {
            double aa = (lane < THREADS / 32) ? sh_s[lane] : 0.0;
            double kk = (lane < THREADS / 32) ? sh_k[lane] : 0.0;
#pragma unroll
            for (int o = 2; o > 0; o >>= 1) {
                aa += __shfl_down_sync(0xFFFFFFFFu, aa, o);
                kk += __shfl_down_sync(0xFFFFFFFFu, kk, o);
            }
            if (lane == 0) {
                out[0] = (float)(aa / kk);
                g_count = 0;                    // rearm for next replay
            }
        }
    }
}

extern "C" void kernel_launch(void* const* d_in, const int* in_sizes, int n_in,
                              void* d_out, int out_size) {
    const float4* emb = (const float4*)d_in[0]; // [8,256,128,128] f32
    const int4*   lb  = (const int4*)d_in[1];   // [8,128,128] i32
    const float*  Q   = (const float*)d_in[2];  // [19,256] f32
    float*        out = (float*)d_out;          // scalar f32

    (void)in_sizes; (void)n_in; (void)out_size;

    ppd_fused<<<NBLOCKS, THREADS>>>(emb, lb, Q, out);
}

// round 8
// speedup vs baseline: 1.1635x; 1.0203x over previous
#include <cuda_runtime.h>

// PixelPrototypeDistanceLoss — B=8, D=256, H=W=128, C=19, IGNORE=19
// loss = mean over valid pixels of (1 - emb[b,:,h,w] . Q[lb]) ^ 2
//
// R8: d-split blocks to fix occupancy (R7: occ=10.9% ~ 7 warps/SM -> dead FMA
// phases uncovered -> avg bytes-in-flight ~ break-even -> DRAM stuck at 53.5%).
//  - 256 threads/block: warps 0-3 do d[0,128), warps 4-7 do d[128,256) for the
//    SAME 512 pixels; partials combined via 2KB SMEM. Warps/SM ~14 (2x R7).
//  - per-thread: one float4 column (4 px), LDG.128 x16-deep batch, imm offsets
//  - Q in SMEM stride 257 (conflict-free gather)
//  - fused last-block-done reduction (counter self-rearms; no spin-waits)
//
// lb is int32 on device (JAX x64 disabled).

constexpr int Bv = 8, Dv = 256, Hv = 128, Wv = 128, Cv = 19, IGNORE = 19;
constexpr int HW = Hv * Wv;                     // 16384
constexpr long long NPIX = (long long)Bv * HW;  // 131072
constexpr int THREADS = 256;                    // 128 pixel-groups x 2 d-halves
constexpr int PG_PER_BLOCK = 128;               // float4 groups (512 px) per block
constexpr int NBLOCKS = (int)(NPIX / (4 * PG_PER_BLOCK));  // 256
constexpr int QSTRIDE = Dv + 1;                 // 257
constexpr int UNROLL = 16;
constexpr int DHALF = Dv / 2;                   // 128 d per half
constexpr int HW4 = HW / 4;                     // float4 stride per d

__device__ float g_bsum[NBLOCKS];
__device__ float g_bcnt[NBLOCKS];
__device__ unsigned int g_count = 0;            // rearmed by last block each launch

__global__ void __launch_bounds__(THREADS, 2)
ppd_fused(const float4* __restrict__ emb4,
          const int4* __restrict__ lb4,
          const float* __restrict__ Q,
          float* __restrict__ out) {
    __shared__ float Qs[Cv * QSTRIDE];          // ~19.5 KB
    __shared__ float s_part[PG_PER_BLOCK * 4];  // 2 KB: upper-half partials
    __shared__ float s_sq[4];                   // 4 active warps in final phase
    __shared__ float s_ct[4];
    __shared__ double sh_s[8];
    __shared__ double sh_k[8];
    __shared__ int s_last;

    const int tid  = threadIdx.x;
    const int pg   = tid & (PG_PER_BLOCK - 1);  // pixel-group 0..127
    const int half = tid >> 7;                  // d-half 0/1 (warps 0-3 / 4-7)

    const int t4 = blockIdx.x * PG_PER_BLOCK + pg;  // global float4-group id
    const int n0 = t4 * 4;

    // labels (both halves load the same int4 — L1 broadcast, negligible)
    const int4 lbv = lb4[t4];
    const bool v0 = lbv.x != IGNORE, v1 = lbv.y != IGNORE,
               v2 = lbv.z != IGNORE, v3 = lbv.w != IGNORE;

    // Stage Q [19,256] -> padded SMEM
    for (int i = tid; i < Cv * Dv; i += THREADS) {
        const int cc = i >> 8;
        const int dd = i & (Dv - 1);
        Qs[cc * QSTRIDE + dd] = Q[i];
    }
    __syncthreads();

    const float* q0 = &Qs[(v0 ? lbv.x : 0) * QSTRIDE];
    const float* q1 = &Qs[(v1 ? lbv.y : 0) * QSTRIDE];
    const float* q2 = &Qs[(v2 ? lbv.z : 0) * QSTRIDE];
    const float* q3 = &Qs[(v3 ? lbv.w : 0) * QSTRIDE];

    const int b  = n0 >> 14;                    // blocks never straddle images
    const int hw = n0 & (HW - 1);
    const int dbase = half * DHALF;
    const float4* ep = emb4 + ((long long)b * Dv * HW + hw) / 4
                            + (long long)dbase * HW4;

    float a0 = 0.f, a1 = 0.f, a2 = 0.f, a3 = 0.f;

    for (int d0 = 0; d0 < DHALF; d0 += UNROLL) {
        float4 v[UNROLL];
#pragma unroll
        for (int j = 0; j < UNROLL; ++j)
            v[j] = __ldcs(ep + (long long)(d0 + j) * HW4);  // LDG.128, imm offs
#pragma unroll
        for (int j = 0; j < UNROLL; ++j) {
            const int d = dbase + d0 + j;
            a0 = fmaf(v[j].x, q0[d], a0);
            a1 = fmaf(v[j].y, q1[d], a1);
            a2 = fmaf(v[j].z, q2[d], a2);
            a3 = fmaf(v[j].w, q3[d], a3);
        }
    }

    // combine halves: upper warps deposit, lower warps add
    if (half == 1) {
        s_part[pg * 4 + 0] = a0;
        s_part[pg * 4 + 1] = a1;
        s_part[pg * 4 + 2] = a2;
        s_part[pg * 4 + 3] = a3;
    }
    __syncthreads();

    const int wid  = tid >> 5;
    const int lane = tid & 31;

    if (half == 0) {                            // warps 0-3 finish the loss
        a0 += s_part[pg * 4 + 0];
        a1 += s_part[pg * 4 + 1];
        a2 += s_part[pg * 4 + 2];
        a3 += s_part[pg * 4 + 3];

        const float r0 = 1.f - a0, r1 = 1.f - a1, r2 = 1.f - a2, r3 = 1.f - a3;
        float sq  = (v0 ? r0 * r0 : 0.f) + (v1 ? r1 * r1 : 0.f)
                  + (v2 ? r2 * r2 : 0.f) + (v3 ? r3 * r3 : 0.f);
        float cnt = (float)v0 + (float)v1 + (float)v2 + (float)v3;

#pragma unroll
        for (int o = 16; o > 0; o >>= 1) {
            sq  += __shfl_down_sync(0xFFFFFFFFu, sq,  o);
            cnt += __shfl_down_sync(0xFFFFFFFFu, cnt, o);
        }
        if (lane == 0) { s_sq[wid] = sq; s_ct[wid] = cnt; }
    }
    __syncthreads();

    if (tid == 0) {
        float s = 0.f, k = 0.f;
#pragma unroll
        for (int w = 0; w < 4; ++w) { s += s_sq[w]; k += s_ct[w]; }
        g_bsum[blockIdx.x] = s;
        g_bcnt[blockIdx.x] = k;
        __threadfence();
        const unsigned prev = atomicAdd(&g_count, 1u);
        s_last = (prev == (unsigned)(NBLOCKS - 1));
    }
    __syncthreads();

    if (s_last) {                               // last block reduces 256 partials
        double a = 0.0, k = 0.0;
        for (int i = tid; i < NBLOCKS; i += THREADS) {
            a += (double)__ldcg(&g_bsum[i]);
            k += (double)__ldcg(&g_bcnt[i]);
        }
#pragma unroll
        for (int o = 16; o > 0; o >>= 1) {
            a += __shfl_down_sync(0xFFFFFFFFu, a, o);
            k += __shfl_down_sync(0xFFFFFFFFu, k, o);
        }
        if (lane == 0) { sh_s[wid] = a; sh_k[wid] = k; }
        __syncthreads();
        if (wid == 0) {
            double aa = (lane < THREADS / 32) ? sh_s[lane] : 0.0;
            double kk = (lane < THREADS / 32) ? sh_k[lane] : 0.0;
#pragma unroll
            for (int o = 4; o > 0; o >>= 1) {
                aa += __shfl_down_sync(0xFFFFFFFFu, aa, o);
                kk += __shfl_down_sync(0xFFFFFFFFu, kk, o);
            }
            if (lane == 0) {
                out[0] = (float)(aa / kk);
                g_count = 0;                    // rearm for next replay
            }
        }
    }
}

extern "C" void kernel_launch(void* const* d_in, const int* in_sizes, int n_in,
                              void* d_out, int out_size) {
    const float4* emb = (const float4*)d_in[0]; // [8,256,128,128] f32
    const int4*   lb  = (const int4*)d_in[1];   // [8,128,128] i32
    const float*  Q   = (const float*)d_in[2];  // [19,256] f32
    float*        out = (float*)d_out;          // scalar f32

    (void)in_sizes; (void)n_in; (void)out_size;

    ppd_fused<<<NBLOCKS, THREADS>>>(emb, lb, Q, out);
}

// round 9
// speedup vs baseline: 1.1672x; 1.0032x over previous
#include <cuda_runtime.h>

// PixelPrototypeDistanceLoss — B=8, D=256, H=W=128, C=19, IGNORE=19
// loss = mean over valid pixels of (1 - emb[b,:,h,w] . Q[lb]) ^ 2
//
// R9: software-pipelined double buffer (R8 post-mortem: warp-count doubling did
// NOT raise DRAM% -> limiter is the batch sawtooth: 0 bytes in flight during the
// consume phase. Two 8-deep float4 buffers, prefetch/consume interleaved ->
// sustained ~4KB/warp in flight, ~56KB/SM >> ~25KB latency-BW product).
//  - 256 threads/block: warps 0-3 d[0,128), warps 4-7 d[128,256), same 512 px
//  - LDG.128 __ldcs, immediate d-offsets
//  - Q in SMEM stride 257 (conflict-free gather)
//  - fused last-block-done reduction (counter self-rearms; no spin-waits)
//
// lb is int32 on device (JAX x64 disabled).

constexpr int Bv = 8, Dv = 256, Hv = 128, Wv = 128, Cv = 19, IGNORE = 19;
constexpr int HW = Hv * Wv;                     // 16384
constexpr long long NPIX = (long long)Bv * HW;  // 131072
constexpr int THREADS = 256;                    // 128 pixel-groups x 2 d-halves
constexpr int PG_PER_BLOCK = 128;               // float4 groups (512 px) per block
constexpr int NBLOCKS = (int)(NPIX / (4 * PG_PER_BLOCK));  // 256
constexpr int QSTRIDE = Dv + 1;                 // 257
constexpr int NB = 8;                           // pipeline buffer depth
constexpr int DHALF = Dv / 2;                   // 128 d per half
constexpr int HW4 = HW / 4;                     // float4 stride per d
constexpr int NCHUNK = DHALF / (2 * NB);        // 8 double-chunks

__device__ float g_bsum[NBLOCKS];
__device__ float g_bcnt[NBLOCKS];
__device__ unsigned int g_count = 0;            // rearmed by last block each launch

__global__ void __launch_bounds__(THREADS, 2)
ppd_fused(const float4* __restrict__ emb4,
          const int4* __restrict__ lb4,
          const float* __restrict__ Q,
          float* __restrict__ out) {
    __shared__ float Qs[Cv * QSTRIDE];          // ~19.5 KB
    __shared__ float s_part[PG_PER_BLOCK * 4];  // 2 KB upper-half partials
    __shared__ float s_sq[4];
    __shared__ float s_ct[4];
    __shared__ double sh_s[8];
    __shared__ double sh_k[8];
    __shared__ int s_last;

    const int tid  = threadIdx.x;
    const int pg   = tid & (PG_PER_BLOCK - 1);  // pixel-group 0..127
    const int half = tid >> 7;                  // d-half 0/1

    const int t4 = blockIdx.x * PG_PER_BLOCK + pg;
    const int n0 = t4 * 4;

    const int4 lbv = lb4[t4];
    const bool v0 = lbv.x != IGNORE, v1 = lbv.y != IGNORE,
               v2 = lbv.z != IGNORE, v3 = lbv.w != IGNORE;

    for (int i = tid; i < Cv * Dv; i += THREADS) {
        const int cc = i >> 8;
        const int dd = i & (Dv - 1);
        Qs[cc * QSTRIDE + dd] = Q[i];
    }
    __syncthreads();

    const float* q0 = &Qs[(v0 ? lbv.x : 0) * QSTRIDE];
    const float* q1 = &Qs[(v1 ? lbv.y : 0) * QSTRIDE];
    const float* q2 = &Qs[(v2 ? lbv.z : 0) * QSTRIDE];
    const float* q3 = &Qs[(v3 ? lbv.w : 0) * QSTRIDE];

    const int b  = n0 >> 14;
    const int hw = n0 & (HW - 1);
    const int dbase = half * DHALF;
    const float4* ep = emb4 + ((long long)b * Dv * HW + hw) / 4
                            + (long long)dbase * HW4;

    float a0 = 0.f, a1 = 0.f, a2 = 0.f, a3 = 0.f;

    float4 va[NB], vb[NB];
    // prologue: fill A with d 0..7
#pragma unroll
    for (int j = 0; j < NB; ++j)
        va[j] = __ldcs(ep + (long long)j * HW4);

#pragma unroll
    for (int c2 = 0; c2 < NCHUNK; ++c2) {
        const int dA = c2 * 2 * NB;             // A holds dA..dA+7

        // prefetch B: dA+8..dA+15
#pragma unroll
        for (int j = 0; j < NB; ++j)
            vb[j] = __ldcs(ep + (long long)(dA + NB + j) * HW4);

        // consume A (B in flight)
#pragma unroll
        for (int j = 0; j < NB; ++j) {
            const int d = dbase + dA + j;
            a0 = fmaf(va[j].x, q0[d], a0);
            a1 = fmaf(va[j].y, q1[d], a1);
            a2 = fmaf(va[j].z, q2[d], a2);
            a3 = fmaf(va[j].w, q3[d], a3);
        }

        // prefetch A for next chunk: dA+16..dA+23 (compile-time guarded)
        if (c2 + 1 < NCHUNK) {
#pragma unroll
            for (int j = 0; j < NB; ++j)
                va[j] = __ldcs(ep + (long long)(dA + 2 * NB + j) * HW4);
        }

        // consume B (next A in flight)
#pragma unroll
        for (int j = 0; j < NB; ++j) {
            const int d = dbase + dA + NB + j;
            a0 = fmaf(vb[j].x, q0[d], a0);
            a1 = fmaf(vb[j].y, q1[d], a1);
            a2 = fmaf(vb[j].z, q2[d], a2);
            a3 = fmaf(vb[j].w, q3[d], a3);
        }
    }

    if (half == 1) {
        s_part[pg * 4 + 0] = a0;
        s_part[pg * 4 + 1] = a1;
        s_part[pg * 4 + 2] = a2;
        s_part[pg * 4 + 3] = a3;
    }
    __syncthreads();

    const int wid  = tid >> 5;
    const int lane = tid & 31;

    if (half == 0) {
        a0 += s_part[pg * 4 + 0];
        a1 += s_part[pg * 4 + 1];
        a2 += s_part[pg * 4 + 2];
        a3 += s_part[pg * 4 + 3];

        const float r0 = 1.f - a0, r1 = 1.f - a1, r2 = 1.f - a2, r3 = 1.f - a3;
        float sq  = (v0 ? r0 * r0 : 0.f) + (v1 ? r1 * r1 : 0.f)
                  + (v2 ? r2 * r2 : 0.f) + (v3 ? r3 * r3 : 0.f);
        float cnt = (float)v0 + (float)v1 + (float)v2 + (float)v3;

#pragma unroll
        for (int o = 16; o > 0; o >>= 1) {
            sq  += __shfl_down_sync(0xFFFFFFFFu, sq,  o);
            cnt += __shfl_down_sync(0xFFFFFFFFu, cnt, o);
        }
        if (lane == 0) { s_sq[wid] = sq; s_ct[wid] = cnt; }
    }
    __syncthreads();

    if (tid == 0) {
        float s = 0.f, k = 0.f;
#pragma unroll
        for (int w = 0; w < 4; ++w) { s += s_sq[w]; k += s_ct[w]; }
        g_bsum[blockIdx.x] = s;
        g_bcnt[blockIdx.x] = k;
        __threadfence();
        const unsigned prev = atomicAdd(&g_count, 1u);
        s_last = (prev == (unsigned)(NBLOCKS - 1));
    }
    __syncthreads();

    if (s_last) {
        double a = 0.0, k = 0.0;
        for (int i = tid; i < NBLOCKS; i += THREADS) {
            a += (double)__ldcg(&g_bsum[i]);
            k += (double)__ldcg(&g_bcnt[i]);
        }
#pragma unroll
        for (int o = 16; o > 0; o >>= 1) {
            a += __shfl_down_sync(0xFFFFFFFFu, a, o);
            k += __shfl_down_sync(0xFFFFFFFFu, k, o);
        }
        if (lane == 0) { sh_s[wid] = a; sh_k[wid] = k; }
        __syncthreads();
        if (wid == 0) {
            double aa = (lane < THREADS / 32) ? sh_s[lane] : 0.0;
            double kk = (lane < THREADS / 32) ? sh_k[lane] : 0.0;
#pragma unroll
            for (int o = 4; o > 0; o >>= 1) {
                aa += __shfl_down_sync(0xFFFFFFFFu, aa, o);
                kk += __shfl_down_sync(0xFFFFFFFFu, kk, o);
            }
            if (lane == 0) {
                out[0] = (float)(aa / kk);
                g_count = 0;
            }
        }
    }
}

extern "C" void kernel_launch(void* const* d_in, const int* in_sizes, int n_in,
                              void* d_out, int out_size) {
    const float4* emb = (const float4*)d_in[0]; // [8,256,128,128] f32
    const int4*   lb  = (const int4*)d_in[1];   // [8,128,128] i32
    const float*  Q   = (const float*)d_in[2];  // [19,256] f32
    float*        out = (float*)d_out;          // scalar f32

    (void)in_sizes; (void)n_in; (void)out_size;

    ppd_fused<<<NBLOCKS, THREADS>>>(emb, lb, Q, out);
}